// round 12
// baseline (speedup 1.0000x reference)
#include <cuda_runtime.h>
#include <cstdint>

// ---------------------------------------------------------------------------
// out[n] = elg[n] @ W @ eth[n],  N=32768, D=1024, fp32.
// R10: persistent-CTA version of R9. Grid 304 (2 CTAs/SM); each CTA strides
// over ~7 (nt, rowblk) work items with ONE continuous 3-stage cp.async ring:
// no pipeline drain between work items, epilogue overlapped with the next
// item's loads. Hot loop unchanged (128x128 tile, 4 fat warps 64x64,
// raw eth + RNA-rounded W). Reduction uses a dedicated smem slab.
// ---------------------------------------------------------------------------

static constexpr int NROWS = 32768;
static constexpr int DDIM  = 1024;
static constexpr int BM = 128, BN = 128, BK = 32;
static constexpr int KITERS = DDIM / BK;             // 32
static constexpr int NWORK  = (DDIM / BN) * (NROWS / BM);  // 2048

static constexpr int ROWF     = 36;                  // 32 floats + 4 pad
static constexpr int A_TILE_B = BM * ROWF * 4;       // 18432
static constexpr int B_TILE_B = BN * ROWF * 4;       // 18432
static constexpr int STAGE_B  = A_TILE_B + B_TILE_B; // 36864
static constexpr int STAGE_F  = STAGE_B / 4;         // 9216 floats
static constexpr int NSTAGES  = 3;
static constexpr int RED_B    = 256 * 4;             // reduction slab
static constexpr int SMEM_B   = NSTAGES * STAGE_B + RED_B;  // 111616

static constexpr int GRID_X   = 304;                 // 2 CTAs/SM x 152 SMs

__device__ float g_W_t[(size_t)DDIM * DDIM];         // 4 MB rounded W

__device__ __forceinline__ uint32_t smem_u32(const void* p) {
    uint32_t a;
    asm("{ .reg .u64 t; cvta.to.shared.u64 t, %1; cvt.u32.u64 %0, t; }" : "=r"(a) : "l"(p));
    return a;
}

__device__ __forceinline__ void cp16(uint32_t saddr, const void* g) {
    asm volatile("cp.async.cg.shared.global [%0], [%1], 16;\n" :: "r"(saddr), "l"(g));
}
#define CP_COMMIT() asm volatile("cp.async.commit_group;\n" ::: "memory")
#define CP_WAIT1()  asm volatile("cp.async.wait_group 1;\n" ::: "memory")
#define CP_WAIT0()  asm volatile("cp.async.wait_group 0;\n" ::: "memory")

__device__ __forceinline__ void ldsm4(uint32_t (&d)[4], uint32_t addr) {
    asm volatile("ldmatrix.sync.aligned.m8n8.x4.shared.b16 {%0,%1,%2,%3}, [%4];"
                 : "=r"(d[0]), "=r"(d[1]), "=r"(d[2]), "=r"(d[3]) : "r"(addr));
}

__device__ __forceinline__ float rna_tf32(float x) {
    uint32_t y;
    asm("cvt.rna.tf32.f32 %0, %1;" : "=r"(y) : "f"(x));
    return __uint_as_float(y);
}

__device__ __forceinline__ void prefetch_l2(const void* p) {
    asm volatile("prefetch.global.L2 [%0];" :: "l"(p));
}

__device__ __forceinline__ void mma_tf32(float (&c)[4], const uint32_t (&a)[4],
                                         uint32_t b0, uint32_t b1) {
    asm volatile(
        "mma.sync.aligned.m16n8k8.row.col.f32.tf32.tf32.f32 "
        "{%0,%1,%2,%3}, {%4,%5,%6,%7}, {%8,%9}, {%0,%1,%2,%3};"
        : "+f"(c[0]), "+f"(c[1]), "+f"(c[2]), "+f"(c[3])
        : "r"(a[0]), "r"(a[1]), "r"(a[2]), "r"(a[3]), "r"(b0), "r"(b1));
}

// ---------------- prep: RNA-round W (4 MB) + zero out (128 KB) -------------

static constexpr int W4   = (DDIM * DDIM) / 4;
static constexpr int OUT4 = NROWS / 4;

__global__ void __launch_bounds__(256)
prep_kernel(const float* __restrict__ Wsrc, float* __restrict__ Wdst,
            float* __restrict__ outz)
{
    const int gid = blockIdx.x * blockDim.x + threadIdx.x;
    const int stride = gridDim.x * blockDim.x;
    for (int i = gid; i < W4; i += stride) {
        float4 v = reinterpret_cast<const float4*>(Wsrc)[i];
        v.x = rna_tf32(v.x); v.y = rna_tf32(v.y);
        v.z = rna_tf32(v.z); v.w = rna_tf32(v.w);
        reinterpret_cast<float4*>(Wdst)[i] = v;
    }
    for (int i = gid; i < OUT4; i += stride)
        reinterpret_cast<float4*>(outz)[i] = make_float4(0.f, 0.f, 0.f, 0.f);
}

// ------------------------------- main kernel -------------------------------

__global__ void __launch_bounds__(128, 2)
bilinear_tf32_kernel(const float* __restrict__ elg, const float* __restrict__ eth,
                     const float* __restrict__ Wm, float* __restrict__ out)
{
    extern __shared__ __align__(16) float smem[];
    const uint32_t sbase = smem_u32(smem);
    float* red = smem + NSTAGES * STAGE_F;     // dedicated reduction slab

    const int tid    = threadIdx.x;
    const int lane   = tid & 31;
    const int wid    = tid >> 5;      // 0..3
    const int warp_m = wid >> 1;      // 0..1
    const int warp_n = wid & 1;       // 0..1
    const int bx     = blockIdx.x;

    const int my_nwork = (NWORK - bx + GRID_X - 1) / GRID_X;   // 6 or 7
    const int gtot     = my_nwork * KITERS;

    // ldmatrix per-lane byte offsets (t = tile index, r = row within tile)
    const int t = lane >> 3, r = lane & 7;
    const uint32_t aoff = (uint32_t)((((t & 1) * 8 + r) * ROWF + (t >> 1) * 4) * 4);
    const uint32_t boff = (uint32_t)((((t >> 1) * 8 + r) * ROWF + (t & 1) * 4) * 4);
    const uint32_t a_warp = (uint32_t)(warp_m * 64 * ROWF * 4);
    const uint32_t b_warp = (uint32_t)(warp_n * 64 * ROWF * 4);

    float acc[4][8][4];
    #pragma unroll
    for (int i = 0; i < 4; ++i)
        #pragma unroll
        for (int j = 0; j < 8; ++j)
            #pragma unroll
            for (int k = 0; k < 4; ++k) acc[i][j][k] = 0.0f;

    // Issue cp.async for global iteration jt (work = bx + (jt/32)*GRID_X).
    auto issue = [&](int jt) {
        const int w   = bx + (jt >> 5) * GRID_X;
        const int nt  = w & 7;
        const size_t row0 = (size_t)(w >> 3) * BM;
        const int kc = jt & 31, st = jt % NSTAGES;
        const uint32_t ab = sbase + st * STAGE_B;
        const uint32_t bb = ab + A_TILE_B;
        #pragma unroll
        for (int u = 0; u < 8; ++u) {               // A: 128 rows x 8 float4 (raw eth)
            const int idx = tid + u * 128;
            const int m = idx >> 3, c4 = idx & 7;
            cp16(ab + (uint32_t)((m * ROWF + c4 * 4) * 4),
                 eth + (row0 + m) * (size_t)DDIM + kc * BK + c4 * 4);
        }
        #pragma unroll
        for (int u = 0; u < 8; ++u) {               // B: 128 rows x 8 float4 (rounded W)
            const int idx = tid + u * 128;
            const int n = idx >> 3, c4 = idx & 7;
            cp16(bb + (uint32_t)((n * ROWF + c4 * 4) * 4),
                 Wm + (size_t)(nt * BN + n) * DDIM + kc * BK + c4 * 4);
        }
        CP_COMMIT();
    };

    issue(0);
    issue(1);

    for (int gt = 0; gt < gtot; ++gt) {
        const int w   = bx + (gt >> 5) * GRID_X;
        const int nt  = w & 7;
        const size_t row0 = (size_t)(w >> 3) * BM;
        const int kc  = gt & 31;
        const int cur = gt % NSTAGES;

        if (gt == gtot - 1) { CP_WAIT0(); } else { CP_WAIT1(); }
        __syncthreads();

        if (gt + 2 < gtot) issue(gt + 2);

        // Prefetch this work item's epilogue elg block into L2.
        if (kc == 27) {
            const int q = lane & 3, grp = lane >> 2;
            const int col = nt * BN + warp_n * 64 + q * 2;
            #pragma unroll
            for (int fm = 0; fm < 4; ++fm) {
                const size_t rowA = row0 + warp_m * 64 + fm * 16 + grp;
                prefetch_l2(elg + rowA * (size_t)DDIM + col);
                prefetch_l2(elg + (rowA + 8) * (size_t)DDIM + col);
            }
        }

        const uint32_t abase = sbase + cur * STAGE_B + a_warp + aoff;
        const uint32_t bbase = sbase + cur * STAGE_B + A_TILE_B + b_warp + boff;

        #pragma unroll
        for (int ks = 0; ks < 4; ++ks) {
            uint32_t afr[4][4];
            #pragma unroll
            for (int fm = 0; fm < 4; ++fm)
                ldsm4(afr[fm], abase + (uint32_t)(fm * 16 * ROWF * 4 + ks * 32));
            uint32_t bfr[4][4];
            #pragma unroll
            for (int fp = 0; fp < 4; ++fp)
                ldsm4(bfr[fp], bbase + (uint32_t)(fp * 16 * ROWF * 4 + ks * 32));
            #pragma unroll
            for (int fm = 0; fm < 4; ++fm)
                #pragma unroll
                for (int fn = 0; fn < 8; ++fn)
                    mma_tf32(acc[fm][fn], afr[fm],
                             bfr[fn >> 1][(fn & 1) * 2 + 0],
                             bfr[fn >> 1][(fn & 1) * 2 + 1]);
        }

        // End of this work item: fused epilogue (overlaps next item's loads).
        if (kc == KITERS - 1) {
            float part[8];
            #pragma unroll
            for (int i = 0; i < 8; ++i) part[i] = 0.0f;
            const int q = lane & 3, grp = lane >> 2;
            #pragma unroll
            for (int fm = 0; fm < 4; ++fm) {
                const size_t rowA = row0 + warp_m * 64 + fm * 16 + grp;
                #pragma unroll
                for (int fn = 0; fn < 8; ++fn) {
                    const int col = nt * BN + warp_n * 64 + fn * 8 + q * 2;
                    const float2 e0 = *reinterpret_cast<const float2*>(
                        elg + rowA * (size_t)DDIM + col);
                    const float2 e1 = *reinterpret_cast<const float2*>(
                        elg + (rowA + 8) * (size_t)DDIM + col);
                    part[fm * 2 + 0] = fmaf(acc[fm][fn][0], e0.x,
                                       fmaf(acc[fm][fn][1], e0.y, part[fm * 2 + 0]));
                    part[fm * 2 + 1] = fmaf(acc[fm][fn][2], e1.x,
                                       fmaf(acc[fm][fn][3], e1.y, part[fm * 2 + 1]));
                    acc[fm][fn][0] = 0.0f; acc[fm][fn][1] = 0.0f;
                    acc[fm][fn][2] = 0.0f; acc[fm][fn][3] = 0.0f;
                }
            }

            #pragma unroll
            for (int i = 0; i < 8; ++i) {
                part[i] += __shfl_xor_sync(0xFFFFFFFFu, part[i], 1);
                part[i] += __shfl_xor_sync(0xFFFFFFFFu, part[i], 2);
            }
            __syncthreads();          // red slab free (prev work's adds done)
            if ((lane & 3) == 0) {
                #pragma unroll
                for (int fm = 0; fm < 4; ++fm) {
                    red[warp_n * 128 + warp_m * 64 + fm * 16 + grp]     = part[fm * 2 + 0];
                    red[warp_n * 128 + warp_m * 64 + fm * 16 + grp + 8] = part[fm * 2 + 1];
                }
            }
            __syncthreads();
            atomicAdd(&out[row0 + tid], red[tid] + red[128 + tid]);
        }
    }
}

// ------------------------------- launch ------------------------------------

extern "C" void kernel_launch(void* const* d_in, const int* in_sizes, int n_in,
                              void* d_out, int out_size) {
    (void)in_sizes; (void)n_in; (void)out_size;
    const float* elg = (const float*)d_in[0];
    const float* eth = (const float*)d_in[1];
    const float* Wm  = (const float*)d_in[2];
    float* out = (float*)d_out;

    float* W_t = nullptr;
    cudaGetSymbolAddress((void**)&W_t, g_W_t);

    prep_kernel<<<152, 256>>>(Wm, W_t, out);

    cudaFuncSetAttribute(bilinear_tf32_kernel,
                         cudaFuncAttributeMaxDynamicSharedMemorySize, SMEM_B);
    bilinear_tf32_kernel<<<GRID_X, 128, SMEM_B>>>(elg, eth, W_t, out);
}

// round 13
// speedup vs baseline: 1.5429x; 1.5429x over previous
#include <cuda_runtime.h>
#include <cstdint>

// ---------------------------------------------------------------------------
// out[n] = elg[n] @ W @ eth[n],  N=32768, D=1024, fp32.
// R11: R10 persistent-CTA kernel with GRID_X=296 (= 2 x 148 SMs; fully
// resident in ONE wave whether the part has 148 or 152 SMs — R10's 304
// created a serialized second wave on a 148-SM part). Each CTA strides over
// ~7 (nt fixed, rowblk += 37) work items with one continuous 3-stage
// cp.async ring; epilogues overlap the next item's loads. Hot loop unchanged
// (128x128 tile, 4 fat warps 64x64, raw eth + RNA-rounded W).
// ---------------------------------------------------------------------------

static constexpr int NROWS = 32768;
static constexpr int DDIM  = 1024;
static constexpr int BM = 128, BN = 128, BK = 32;
static constexpr int KITERS = DDIM / BK;             // 32
static constexpr int NWORK  = (DDIM / BN) * (NROWS / BM);  // 2048

static constexpr int ROWF     = 36;                  // 32 floats + 4 pad
static constexpr int A_TILE_B = BM * ROWF * 4;       // 18432
static constexpr int B_TILE_B = BN * ROWF * 4;       // 18432
static constexpr int STAGE_B  = A_TILE_B + B_TILE_B; // 36864
static constexpr int STAGE_F  = STAGE_B / 4;         // 9216 floats
static constexpr int NSTAGES  = 3;
static constexpr int RED_B    = 256 * 4;             // reduction slab
static constexpr int SMEM_B   = NSTAGES * STAGE_B + RED_B;  // 111616

static constexpr int GRID_X   = 296;                 // 2 x 148 — one wave on 148 or 152 SMs

__device__ float g_W_t[(size_t)DDIM * DDIM];         // 4 MB rounded W

__device__ __forceinline__ uint32_t smem_u32(const void* p) {
    uint32_t a;
    asm("{ .reg .u64 t; cvta.to.shared.u64 t, %1; cvt.u32.u64 %0, t; }" : "=r"(a) : "l"(p));
    return a;
}

__device__ __forceinline__ void cp16(uint32_t saddr, const void* g) {
    asm volatile("cp.async.cg.shared.global [%0], [%1], 16;\n" :: "r"(saddr), "l"(g));
}
#define CP_COMMIT() asm volatile("cp.async.commit_group;\n" ::: "memory")
#define CP_WAIT1()  asm volatile("cp.async.wait_group 1;\n" ::: "memory")
#define CP_WAIT0()  asm volatile("cp.async.wait_group 0;\n" ::: "memory")

__device__ __forceinline__ void ldsm4(uint32_t (&d)[4], uint32_t addr) {
    asm volatile("ldmatrix.sync.aligned.m8n8.x4.shared.b16 {%0,%1,%2,%3}, [%4];"
                 : "=r"(d[0]), "=r"(d[1]), "=r"(d[2]), "=r"(d[3]) : "r"(addr));
}

__device__ __forceinline__ float rna_tf32(float x) {
    uint32_t y;
    asm("cvt.rna.tf32.f32 %0, %1;" : "=r"(y) : "f"(x));
    return __uint_as_float(y);
}

__device__ __forceinline__ void prefetch_l2(const void* p) {
    asm volatile("prefetch.global.L2 [%0];" :: "l"(p));
}

__device__ __forceinline__ void mma_tf32(float (&c)[4], const uint32_t (&a)[4],
                                         uint32_t b0, uint32_t b1) {
    asm volatile(
        "mma.sync.aligned.m16n8k8.row.col.f32.tf32.tf32.f32 "
        "{%0,%1,%2,%3}, {%4,%5,%6,%7}, {%8,%9}, {%0,%1,%2,%3};"
        : "+f"(c[0]), "+f"(c[1]), "+f"(c[2]), "+f"(c[3])
        : "r"(a[0]), "r"(a[1]), "r"(a[2]), "r"(a[3]), "r"(b0), "r"(b1));
}

// ---------------- prep: RNA-round W (4 MB) + zero out (128 KB) -------------

static constexpr int W4   = (DDIM * DDIM) / 4;
static constexpr int OUT4 = NROWS / 4;

__global__ void __launch_bounds__(256)
prep_kernel(const float* __restrict__ Wsrc, float* __restrict__ Wdst,
            float* __restrict__ outz)
{
    const int gid = blockIdx.x * blockDim.x + threadIdx.x;
    const int stride = gridDim.x * blockDim.x;
    for (int i = gid; i < W4; i += stride) {
        float4 v = reinterpret_cast<const float4*>(Wsrc)[i];
        v.x = rna_tf32(v.x); v.y = rna_tf32(v.y);
        v.z = rna_tf32(v.z); v.w = rna_tf32(v.w);
        reinterpret_cast<float4*>(Wdst)[i] = v;
    }
    for (int i = gid; i < OUT4; i += stride)
        reinterpret_cast<float4*>(outz)[i] = make_float4(0.f, 0.f, 0.f, 0.f);
}

// ------------------------------- main kernel -------------------------------

__global__ void __launch_bounds__(128, 2)
bilinear_tf32_kernel(const float* __restrict__ elg, const float* __restrict__ eth,
                     const float* __restrict__ Wm, float* __restrict__ out)
{
    extern __shared__ __align__(16) float smem[];
    const uint32_t sbase = smem_u32(smem);
    float* red = smem + NSTAGES * STAGE_F;     // dedicated reduction slab

    const int tid    = threadIdx.x;
    const int lane   = tid & 31;
    const int wid    = tid >> 5;      // 0..3
    const int warp_m = wid >> 1;      // 0..1
    const int warp_n = wid & 1;       // 0..1
    const int bx     = blockIdx.x;

    const int my_nwork = (NWORK - bx + GRID_X - 1) / GRID_X;   // 6 or 7
    const int gtot     = my_nwork * KITERS;

    // ldmatrix per-lane byte offsets (t = tile index, r = row within tile)
    const int t = lane >> 3, r = lane & 7;
    const uint32_t aoff = (uint32_t)((((t & 1) * 8 + r) * ROWF + (t >> 1) * 4) * 4);
    const uint32_t boff = (uint32_t)((((t >> 1) * 8 + r) * ROWF + (t & 1) * 4) * 4);
    const uint32_t a_warp = (uint32_t)(warp_m * 64 * ROWF * 4);
    const uint32_t b_warp = (uint32_t)(warp_n * 64 * ROWF * 4);

    float acc[4][8][4];
    #pragma unroll
    for (int i = 0; i < 4; ++i)
        #pragma unroll
        for (int j = 0; j < 8; ++j)
            #pragma unroll
            for (int k = 0; k < 4; ++k) acc[i][j][k] = 0.0f;

    // Issue cp.async for global iteration jt (work = bx + (jt/32)*GRID_X).
    auto issue = [&](int jt) {
        const int w   = bx + (jt >> 5) * GRID_X;
        const int nt  = w & 7;
        const size_t row0 = (size_t)(w >> 3) * BM;
        const int kc = jt & 31, st = jt % NSTAGES;
        const uint32_t ab = sbase + st * STAGE_B;
        const uint32_t bb = ab + A_TILE_B;
        #pragma unroll
        for (int u = 0; u < 8; ++u) {               // A: 128 rows x 8 float4 (raw eth)
            const int idx = tid + u * 128;
            const int m = idx >> 3, c4 = idx & 7;
            cp16(ab + (uint32_t)((m * ROWF + c4 * 4) * 4),
                 eth + (row0 + m) * (size_t)DDIM + kc * BK + c4 * 4);
        }
        #pragma unroll
        for (int u = 0; u < 8; ++u) {               // B: 128 rows x 8 float4 (rounded W)
            const int idx = tid + u * 128;
            const int n = idx >> 3, c4 = idx & 7;
            cp16(bb + (uint32_t)((n * ROWF + c4 * 4) * 4),
                 Wm + (size_t)(nt * BN + n) * DDIM + kc * BK + c4 * 4);
        }
        CP_COMMIT();
    };

    issue(0);
    issue(1);

    for (int gt = 0; gt < gtot; ++gt) {
        const int w   = bx + (gt >> 5) * GRID_X;
        const int nt  = w & 7;
        const size_t row0 = (size_t)(w >> 3) * BM;
        const int kc  = gt & 31;
        const int cur = gt % NSTAGES;

        if (gt == gtot - 1) { CP_WAIT0(); } else { CP_WAIT1(); }
        __syncthreads();

        if (gt + 2 < gtot) issue(gt + 2);

        // Prefetch this work item's epilogue elg block into L2.
        if (kc == 27) {
            const int q = lane & 3, grp = lane >> 2;
            const int col = nt * BN + warp_n * 64 + q * 2;
            #pragma unroll
            for (int fm = 0; fm < 4; ++fm) {
                const size_t rowA = row0 + warp_m * 64 + fm * 16 + grp;
                prefetch_l2(elg + rowA * (size_t)DDIM + col);
                prefetch_l2(elg + (rowA + 8) * (size_t)DDIM + col);
            }
        }

        const uint32_t abase = sbase + cur * STAGE_B + a_warp + aoff;
        const uint32_t bbase = sbase + cur * STAGE_B + A_TILE_B + b_warp + boff;

        #pragma unroll
        for (int ks = 0; ks < 4; ++ks) {
            uint32_t afr[4][4];
            #pragma unroll
            for (int fm = 0; fm < 4; ++fm)
                ldsm4(afr[fm], abase + (uint32_t)(fm * 16 * ROWF * 4 + ks * 32));
            uint32_t bfr[4][4];
            #pragma unroll
            for (int fp = 0; fp < 4; ++fp)
                ldsm4(bfr[fp], bbase + (uint32_t)(fp * 16 * ROWF * 4 + ks * 32));
            #pragma unroll
            for (int fm = 0; fm < 4; ++fm)
                #pragma unroll
                for (int fn = 0; fn < 8; ++fn)
                    mma_tf32(acc[fm][fn], afr[fm],
                             bfr[fn >> 1][(fn & 1) * 2 + 0],
                             bfr[fn >> 1][(fn & 1) * 2 + 1]);
        }

        // End of this work item: fused epilogue (overlaps next item's loads).
        if (kc == KITERS - 1) {
            float part[8];
            #pragma unroll
            for (int i = 0; i < 8; ++i) part[i] = 0.0f;
            const int q = lane & 3, grp = lane >> 2;
            #pragma unroll
            for (int fm = 0; fm < 4; ++fm) {
                const size_t rowA = row0 + warp_m * 64 + fm * 16 + grp;
                #pragma unroll
                for (int fn = 0; fn < 8; ++fn) {
                    const int col = nt * BN + warp_n * 64 + fn * 8 + q * 2;
                    const float2 e0 = *reinterpret_cast<const float2*>(
                        elg + rowA * (size_t)DDIM + col);
                    const float2 e1 = *reinterpret_cast<const float2*>(
                        elg + (rowA + 8) * (size_t)DDIM + col);
                    part[fm * 2 + 0] = fmaf(acc[fm][fn][0], e0.x,
                                       fmaf(acc[fm][fn][1], e0.y, part[fm * 2 + 0]));
                    part[fm * 2 + 1] = fmaf(acc[fm][fn][2], e1.x,
                                       fmaf(acc[fm][fn][3], e1.y, part[fm * 2 + 1]));
                    acc[fm][fn][0] = 0.0f; acc[fm][fn][1] = 0.0f;
                    acc[fm][fn][2] = 0.0f; acc[fm][fn][3] = 0.0f;
                }
            }

            #pragma unroll
            for (int i = 0; i < 8; ++i) {
                part[i] += __shfl_xor_sync(0xFFFFFFFFu, part[i], 1);
                part[i] += __shfl_xor_sync(0xFFFFFFFFu, part[i], 2);
            }
            __syncthreads();          // red slab free (prev work's adds done)
            if ((lane & 3) == 0) {
                #pragma unroll
                for (int fm = 0; fm < 4; ++fm) {
                    red[warp_n * 128 + warp_m * 64 + fm * 16 + grp]     = part[fm * 2 + 0];
                    red[warp_n * 128 + warp_m * 64 + fm * 16 + grp + 8] = part[fm * 2 + 1];
                }
            }
            __syncthreads();
            atomicAdd(&out[row0 + tid], red[tid] + red[128 + tid]);
        }
    }
}

// ------------------------------- launch ------------------------------------

extern "C" void kernel_launch(void* const* d_in, const int* in_sizes, int n_in,
                              void* d_out, int out_size) {
    (void)in_sizes; (void)n_in; (void)out_size;
    const float* elg = (const float*)d_in[0];
    const float* eth = (const float*)d_in[1];
    const float* Wm  = (const float*)d_in[2];
    float* out = (float*)d_out;

    float* W_t = nullptr;
    cudaGetSymbolAddress((void**)&W_t, g_W_t);

    prep_kernel<<<148, 256>>>(Wm, W_t, out);

    cudaFuncSetAttribute(bilinear_tf32_kernel,
                         cudaFuncAttributeMaxDynamicSharedMemorySize, SMEM_B);
    bilinear_tf32_kernel<<<GRID_X, 128, SMEM_B>>>(elg, eth, W_t, out);
}

// round 14
// speedup vs baseline: 1.8031x; 1.1686x over previous
#include <cuda_runtime.h>
#include <cstdint>

// ---------------------------------------------------------------------------
// out[n] = elg[n] @ W @ eth[n],  N=32768, D=1024, fp32.
// R12: R9 shell (grid (8,256), nt fastest, 128x128 tile, 4 fat warps 64x64,
// 3-stage cp.async, 2 CTAs/SM, raw eth + RNA-rounded W) with a software-
// pipelined inner loop: fragments for k-slice ks+1 are ldmatrix'd before the
// MMAs of slice ks (double-buffered register rings), and the cp.async issue
// for stage it+2 is deferred into the ks=1 slot so it doesn't contend with
// the post-barrier fragment loads on MIO.
// ---------------------------------------------------------------------------

static constexpr int NROWS = 32768;
static constexpr int DDIM  = 1024;
static constexpr int BM = 128, BN = 128, BK = 32;
static constexpr int KITERS  = DDIM / BK;            // 32
static constexpr int TOT_IT  = KITERS;               // one n-tile per CTA

static constexpr int ROWF     = 36;                  // 32 floats + 4 pad
static constexpr int A_TILE_B = BM * ROWF * 4;       // 18432
static constexpr int B_TILE_B = BN * ROWF * 4;       // 18432
static constexpr int STAGE_B  = A_TILE_B + B_TILE_B; // 36864
static constexpr int NSTAGES  = 3;
static constexpr int SMEM_B   = NSTAGES * STAGE_B;   // 110592

__device__ float g_W_t[(size_t)DDIM * DDIM];         // 4 MB rounded W

__device__ __forceinline__ uint32_t smem_u32(const void* p) {
    uint32_t a;
    asm("{ .reg .u64 t; cvta.to.shared.u64 t, %1; cvt.u32.u64 %0, t; }" : "=r"(a) : "l"(p));
    return a;
}

__device__ __forceinline__ void cp16(uint32_t saddr, const void* g) {
    asm volatile("cp.async.cg.shared.global [%0], [%1], 16;\n" :: "r"(saddr), "l"(g));
}
#define CP_COMMIT() asm volatile("cp.async.commit_group;\n" ::: "memory")
#define CP_WAIT1()  asm volatile("cp.async.wait_group 1;\n" ::: "memory")
#define CP_WAIT0()  asm volatile("cp.async.wait_group 0;\n" ::: "memory")

__device__ __forceinline__ void ldsm4(uint32_t (&d)[4], uint32_t addr) {
    asm volatile("ldmatrix.sync.aligned.m8n8.x4.shared.b16 {%0,%1,%2,%3}, [%4];"
                 : "=r"(d[0]), "=r"(d[1]), "=r"(d[2]), "=r"(d[3]) : "r"(addr));
}

__device__ __forceinline__ float rna_tf32(float x) {
    uint32_t y;
    asm("cvt.rna.tf32.f32 %0, %1;" : "=r"(y) : "f"(x));
    return __uint_as_float(y);
}

__device__ __forceinline__ void prefetch_l2(const void* p) {
    asm volatile("prefetch.global.L2 [%0];" :: "l"(p));
}

__device__ __forceinline__ void mma_tf32(float (&c)[4], const uint32_t (&a)[4],
                                         uint32_t b0, uint32_t b1) {
    asm volatile(
        "mma.sync.aligned.m16n8k8.row.col.f32.tf32.tf32.f32 "
        "{%0,%1,%2,%3}, {%4,%5,%6,%7}, {%8,%9}, {%0,%1,%2,%3};"
        : "+f"(c[0]), "+f"(c[1]), "+f"(c[2]), "+f"(c[3])
        : "r"(a[0]), "r"(a[1]), "r"(a[2]), "r"(a[3]), "r"(b0), "r"(b1));
}

// ---------------- prep: RNA-round W (4 MB) + zero out (128 KB) -------------

static constexpr int W4   = (DDIM * DDIM) / 4;
static constexpr int OUT4 = NROWS / 4;

__global__ void __launch_bounds__(256)
prep_kernel(const float* __restrict__ Wsrc, float* __restrict__ Wdst,
            float* __restrict__ outz)
{
    const int gid = blockIdx.x * blockDim.x + threadIdx.x;
    const int stride = gridDim.x * blockDim.x;
    for (int i = gid; i < W4; i += stride) {
        float4 v = reinterpret_cast<const float4*>(Wsrc)[i];
        v.x = rna_tf32(v.x); v.y = rna_tf32(v.y);
        v.z = rna_tf32(v.z); v.w = rna_tf32(v.w);
        reinterpret_cast<float4*>(Wdst)[i] = v;
    }
    for (int i = gid; i < OUT4; i += stride)
        reinterpret_cast<float4*>(outz)[i] = make_float4(0.f, 0.f, 0.f, 0.f);
}

// ------------------------------- main kernel -------------------------------

__global__ void __launch_bounds__(128, 2)
bilinear_tf32_kernel(const float* __restrict__ elg, const float* __restrict__ eth,
                     const float* __restrict__ Wm, float* __restrict__ out)
{
    extern __shared__ __align__(16) float smem[];
    const uint32_t sbase = smem_u32(smem);

    const int tid    = threadIdx.x;
    const int lane   = tid & 31;
    const int wid    = tid >> 5;      // 0..3
    const int warp_m = wid >> 1;      // 0..1
    const int warp_n = wid & 1;       // 0..1
    const int nt     = blockIdx.x;    // 0..7 (fastest-varying)
    const size_t row0 = (size_t)blockIdx.y * BM;

    // ldmatrix per-lane byte offsets (t = tile index, r = row within tile)
    const int t = lane >> 3, r = lane & 7;
    const uint32_t aoff = (uint32_t)((((t & 1) * 8 + r) * ROWF + (t >> 1) * 4) * 4);
    const uint32_t boff = (uint32_t)((((t >> 1) * 8 + r) * ROWF + (t & 1) * 4) * 4);
    const uint32_t a_warp = (uint32_t)(warp_m * 64 * ROWF * 4);
    const uint32_t b_warp = (uint32_t)(warp_n * 64 * ROWF * 4);

    float acc[4][8][4];
    #pragma unroll
    for (int i = 0; i < 4; ++i)
        #pragma unroll
        for (int j = 0; j < 8; ++j)
            #pragma unroll
            for (int k = 0; k < 4; ++k) acc[i][j][k] = 0.0f;

    auto issue = [&](int jt) {
        const int kc = jt, st = jt % NSTAGES;
        const uint32_t ab = sbase + st * STAGE_B;
        const uint32_t bb = ab + A_TILE_B;
        #pragma unroll
        for (int u = 0; u < 8; ++u) {               // A: 128 rows x 8 float4 (raw eth)
            const int idx = tid + u * 128;          // 0..1023
            const int m = idx >> 3, c4 = idx & 7;
            cp16(ab + (uint32_t)((m * ROWF + c4 * 4) * 4),
                 eth + (row0 + m) * (size_t)DDIM + kc * BK + c4 * 4);
        }
        #pragma unroll
        for (int u = 0; u < 8; ++u) {               // B: 128 rows x 8 float4 (rounded W)
            const int idx = tid + u * 128;
            const int n = idx >> 3, c4 = idx & 7;
            cp16(bb + (uint32_t)((n * ROWF + c4 * 4) * 4),
                 Wm + (size_t)(nt * BN + n) * DDIM + kc * BK + c4 * 4);
        }
        CP_COMMIT();
    };

    issue(0);
    issue(1);

    int cur = 0;
    for (int it = 0; it < TOT_IT; ++it) {
        if (it == TOT_IT - 1) { CP_WAIT0(); } else { CP_WAIT1(); }
        __syncthreads();

        // Prefetch epilogue elg block into L2 a few iterations early.
        if (it == 27) {
            const int q = lane & 3, grp = lane >> 2;
            const int col = nt * BN + warp_n * 64 + q * 2;
            #pragma unroll
            for (int fm = 0; fm < 4; ++fm) {
                const size_t rowA = row0 + warp_m * 64 + fm * 16 + grp;
                prefetch_l2(elg + rowA * (size_t)DDIM + col);
                prefetch_l2(elg + (rowA + 8) * (size_t)DDIM + col);
            }
        }

        const uint32_t abase = sbase + cur * STAGE_B + a_warp + aoff;
        const uint32_t bbase = sbase + cur * STAGE_B + A_TILE_B + b_warp + boff;

        // Software-pipelined k-slices: double-buffered fragment registers.
        uint32_t afr[2][4][4];
        uint32_t bfr[2][4][4];
        #pragma unroll
        for (int fm = 0; fm < 4; ++fm)
            ldsm4(afr[0][fm], abase + (uint32_t)(fm * 16 * ROWF * 4));
        #pragma unroll
        for (int fp = 0; fp < 4; ++fp)
            ldsm4(bfr[0][fp], bbase + (uint32_t)(fp * 16 * ROWF * 4));

        #pragma unroll
        for (int ks = 0; ks < 4; ++ks) {
            const int cb = ks & 1, nb = cb ^ 1;
            if (ks < 3) {
                #pragma unroll
                for (int fm = 0; fm < 4; ++fm)
                    ldsm4(afr[nb][fm],
                          abase + (uint32_t)(fm * 16 * ROWF * 4 + (ks + 1) * 32));
                #pragma unroll
                for (int fp = 0; fp < 4; ++fp)
                    ldsm4(bfr[nb][fp],
                          bbase + (uint32_t)(fp * 16 * ROWF * 4 + (ks + 1) * 32));
            }
            // Deferred cp.async burst: off the critical post-barrier path.
            if (ks == 1 && it + 2 < TOT_IT) issue(it + 2);

            #pragma unroll
            for (int fm = 0; fm < 4; ++fm)
                #pragma unroll
                for (int fn = 0; fn < 8; ++fn)
                    mma_tf32(acc[fm][fn], afr[cb][fm],
                             bfr[cb][fn >> 1][(fn & 1) * 2 + 0],
                             bfr[cb][fn >> 1][(fn & 1) * 2 + 1]);
        }
        cur = (cur + 1 == NSTAGES) ? 0 : cur + 1;
    }

    // Epilogue: fold acc into per-row partials against elg, reduce, atomicAdd.
    float part[8];
    #pragma unroll
    for (int i = 0; i < 8; ++i) part[i] = 0.0f;
    {
        const int q = lane & 3, grp = lane >> 2;
        #pragma unroll
        for (int fm = 0; fm < 4; ++fm) {
            const size_t rowA = row0 + warp_m * 64 + fm * 16 + grp;
            #pragma unroll
            for (int fn = 0; fn < 8; ++fn) {
                const int col = nt * BN + warp_n * 64 + fn * 8 + q * 2;
                const float2 e0 = *reinterpret_cast<const float2*>(
                    elg + rowA * (size_t)DDIM + col);
                const float2 e1 = *reinterpret_cast<const float2*>(
                    elg + (rowA + 8) * (size_t)DDIM + col);
                part[fm * 2 + 0] = fmaf(acc[fm][fn][0], e0.x,
                                   fmaf(acc[fm][fn][1], e0.y, part[fm * 2 + 0]));
                part[fm * 2 + 1] = fmaf(acc[fm][fn][2], e1.x,
                                   fmaf(acc[fm][fn][3], e1.y, part[fm * 2 + 1]));
            }
        }
    }

    __syncthreads();
    #pragma unroll
    for (int i = 0; i < 8; ++i) {
        part[i] += __shfl_xor_sync(0xFFFFFFFFu, part[i], 1);
        part[i] += __shfl_xor_sync(0xFFFFFFFFu, part[i], 2);
    }
    float* red = smem;                // [2][128]
    if ((lane & 3) == 0) {
        const int grp = lane >> 2;
        #pragma unroll
        for (int fm = 0; fm < 4; ++fm) {
            red[warp_n * 128 + warp_m * 64 + fm * 16 + grp]     = part[fm * 2 + 0];
            red[warp_n * 128 + warp_m * 64 + fm * 16 + grp + 8] = part[fm * 2 + 1];
        }
    }
    __syncthreads();
    atomicAdd(&out[row0 + tid], red[tid] + red[128 + tid]);
}

// ------------------------------- launch ------------------------------------

extern "C" void kernel_launch(void* const* d_in, const int* in_sizes, int n_in,
                              void* d_out, int out_size) {
    (void)in_sizes; (void)n_in; (void)out_size;
    const float* elg = (const float*)d_in[0];
    const float* eth = (const float*)d_in[1];
    const float* Wm  = (const float*)d_in[2];
    float* out = (float*)d_out;

    float* W_t = nullptr;
    cudaGetSymbolAddress((void**)&W_t, g_W_t);

    prep_kernel<<<148, 256>>>(Wm, W_t, out);

    cudaFuncSetAttribute(bilinear_tf32_kernel,
                         cudaFuncAttributeMaxDynamicSharedMemorySize, SMEM_B);
    dim3 grid(DDIM / BN, NROWS / BM);   // x = n-tile (fastest), y = row block
    bilinear_tf32_kernel<<<grid, 128, SMEM_B>>>(elg, eth, W_t, out);
}

// round 15
// speedup vs baseline: 1.8430x; 1.0221x over previous
#include <cuda_runtime.h>
#include <cstdint>

// ---------------------------------------------------------------------------
// out[n] = elg[n] @ W @ eth[n],  N=32768, D=1024, fp32.
// R13: R12 with the pipeline rotated across the stage boundary. The
// CP_WAIT + __syncthreads for the next smem stage moves into the ks=3 slot,
// BEFORE the final MMA block: wait -> barrier -> ldsm next stage's ks=0
// fragments -> MMA ks=3 (operands already in registers). Every ldsm chain in
// steady state is covered by in-flight MMAs. Shell unchanged: grid (8,256),
// 128x128 tile, 4 fat warps 64x64, 3-stage cp.async, 2 CTAs/SM, raw eth +
// RNA-rounded W, fused elg epilogue + atomicAdd.
// ---------------------------------------------------------------------------

static constexpr int NROWS = 32768;
static constexpr int DDIM  = 1024;
static constexpr int BM = 128, BN = 128, BK = 32;
static constexpr int KITERS  = DDIM / BK;            // 32
static constexpr int TOT_IT  = KITERS;               // one n-tile per CTA

static constexpr int ROWF     = 36;                  // 32 floats + 4 pad
static constexpr int A_TILE_B = BM * ROWF * 4;       // 18432
static constexpr int B_TILE_B = BN * ROWF * 4;       // 18432
static constexpr int STAGE_B  = A_TILE_B + B_TILE_B; // 36864
static constexpr int NSTAGES  = 3;
static constexpr int SMEM_B   = NSTAGES * STAGE_B;   // 110592

__device__ float g_W_t[(size_t)DDIM * DDIM];         // 4 MB rounded W

__device__ __forceinline__ uint32_t smem_u32(const void* p) {
    uint32_t a;
    asm("{ .reg .u64 t; cvta.to.shared.u64 t, %1; cvt.u32.u64 %0, t; }" : "=r"(a) : "l"(p));
    return a;
}

__device__ __forceinline__ void cp16(uint32_t saddr, const void* g) {
    asm volatile("cp.async.cg.shared.global [%0], [%1], 16;\n" :: "r"(saddr), "l"(g));
}
#define CP_COMMIT() asm volatile("cp.async.commit_group;\n" ::: "memory")
#define CP_WAIT1()  asm volatile("cp.async.wait_group 1;\n" ::: "memory")
#define CP_WAIT0()  asm volatile("cp.async.wait_group 0;\n" ::: "memory")

__device__ __forceinline__ void ldsm4(uint32_t (&d)[4], uint32_t addr) {
    asm volatile("ldmatrix.sync.aligned.m8n8.x4.shared.b16 {%0,%1,%2,%3}, [%4];"
                 : "=r"(d[0]), "=r"(d[1]), "=r"(d[2]), "=r"(d[3]) : "r"(addr));
}

__device__ __forceinline__ float rna_tf32(float x) {
    uint32_t y;
    asm("cvt.rna.tf32.f32 %0, %1;" : "=r"(y) : "f"(x));
    return __uint_as_float(y);
}

__device__ __forceinline__ void prefetch_l2(const void* p) {
    asm volatile("prefetch.global.L2 [%0];" :: "l"(p));
}

__device__ __forceinline__ void mma_tf32(float (&c)[4], const uint32_t (&a)[4],
                                         uint32_t b0, uint32_t b1) {
    asm volatile(
        "mma.sync.aligned.m16n8k8.row.col.f32.tf32.tf32.f32 "
        "{%0,%1,%2,%3}, {%4,%5,%6,%7}, {%8,%9}, {%0,%1,%2,%3};"
        : "+f"(c[0]), "+f"(c[1]), "+f"(c[2]), "+f"(c[3])
        : "r"(a[0]), "r"(a[1]), "r"(a[2]), "r"(a[3]), "r"(b0), "r"(b1));
}

// ---------------- prep: RNA-round W (4 MB) + zero out (128 KB) -------------

static constexpr int W4   = (DDIM * DDIM) / 4;
static constexpr int OUT4 = NROWS / 4;

__global__ void __launch_bounds__(256)
prep_kernel(const float* __restrict__ Wsrc, float* __restrict__ Wdst,
            float* __restrict__ outz)
{
    const int gid = blockIdx.x * blockDim.x + threadIdx.x;
    const int stride = gridDim.x * blockDim.x;
    for (int i = gid; i < W4; i += stride) {
        float4 v = reinterpret_cast<const float4*>(Wsrc)[i];
        v.x = rna_tf32(v.x); v.y = rna_tf32(v.y);
        v.z = rna_tf32(v.z); v.w = rna_tf32(v.w);
        reinterpret_cast<float4*>(Wdst)[i] = v;
    }
    for (int i = gid; i < OUT4; i += stride)
        reinterpret_cast<float4*>(outz)[i] = make_float4(0.f, 0.f, 0.f, 0.f);
}

// ------------------------------- main kernel -------------------------------

__global__ void __launch_bounds__(128, 2)
bilinear_tf32_kernel(const float* __restrict__ elg, const float* __restrict__ eth,
                     const float* __restrict__ Wm, float* __restrict__ out)
{
    extern __shared__ __align__(16) float smem[];
    const uint32_t sbase = smem_u32(smem);

    const int tid    = threadIdx.x;
    const int lane   = tid & 31;
    const int wid    = tid >> 5;      // 0..3
    const int warp_m = wid >> 1;      // 0..1
    const int warp_n = wid & 1;       // 0..1
    const int nt     = blockIdx.x;    // 0..7 (fastest-varying)
    const size_t row0 = (size_t)blockIdx.y * BM;

    // ldmatrix per-lane byte offsets (t = tile index, r = row within tile)
    const int t = lane >> 3, r = lane & 7;
    const uint32_t aoff = (uint32_t)((((t & 1) * 8 + r) * ROWF + (t >> 1) * 4) * 4);
    const uint32_t boff = (uint32_t)((((t >> 1) * 8 + r) * ROWF + (t & 1) * 4) * 4);
    const uint32_t a_warp = (uint32_t)(warp_m * 64 * ROWF * 4);
    const uint32_t b_warp = (uint32_t)(warp_n * 64 * ROWF * 4);

    float acc[4][8][4];
    #pragma unroll
    for (int i = 0; i < 4; ++i)
        #pragma unroll
        for (int j = 0; j < 8; ++j)
            #pragma unroll
            for (int k = 0; k < 4; ++k) acc[i][j][k] = 0.0f;

    auto issue = [&](int jt) {
        const int kc = jt, st = jt % NSTAGES;
        const uint32_t ab = sbase + st * STAGE_B;
        const uint32_t bb = ab + A_TILE_B;
        #pragma unroll
        for (int u = 0; u < 8; ++u) {               // A: 128 rows x 8 float4 (raw eth)
            const int idx = tid + u * 128;          // 0..1023
            const int m = idx >> 3, c4 = idx & 7;
            cp16(ab + (uint32_t)((m * ROWF + c4 * 4) * 4),
                 eth + (row0 + m) * (size_t)DDIM + kc * BK + c4 * 4);
        }
        #pragma unroll
        for (int u = 0; u < 8; ++u) {               // B: 128 rows x 8 float4 (rounded W)
            const int idx = tid + u * 128;
            const int n = idx >> 3, c4 = idx & 7;
            cp16(bb + (uint32_t)((n * ROWF + c4 * 4) * 4),
                 Wm + (size_t)(nt * BN + n) * DDIM + kc * BK + c4 * 4);
        }
        CP_COMMIT();
    };

    issue(0);
    issue(1);

    // Prologue: stage 0 resident, load its ks=0 fragments into buffer 0.
    uint32_t afr[2][4][4];
    uint32_t bfr[2][4][4];

    CP_WAIT1();
    __syncthreads();
    {
        const uint32_t ab0 = sbase + a_warp + aoff;
        const uint32_t bb0 = sbase + A_TILE_B + b_warp + boff;
        #pragma unroll
        for (int fm = 0; fm < 4; ++fm)
            ldsm4(afr[0][fm], ab0 + (uint32_t)(fm * 16 * ROWF * 4));
        #pragma unroll
        for (int fp = 0; fp < 4; ++fp)
            ldsm4(bfr[0][fp], bb0 + (uint32_t)(fp * 16 * ROWF * 4));
    }

    int cur = 0;
    for (int it = 0; it < TOT_IT; ++it) {
        const uint32_t abase = sbase + cur * STAGE_B + a_warp + aoff;
        const uint32_t bbase = sbase + cur * STAGE_B + A_TILE_B + b_warp + boff;
        const int nxt = (cur + 1 == NSTAGES) ? 0 : cur + 1;
        const uint32_t abase_n = sbase + nxt * STAGE_B + a_warp + aoff;
        const uint32_t bbase_n = sbase + nxt * STAGE_B + A_TILE_B + b_warp + boff;

        #pragma unroll
        for (int ks = 0; ks < 4; ++ks) {
            const int cb = ks & 1, nb = cb ^ 1;
            if (ks < 3) {
                // Fragments for k-slice ks+1 of this stage.
                #pragma unroll
                for (int fm = 0; fm < 4; ++fm)
                    ldsm4(afr[nb][fm],
                          abase + (uint32_t)(fm * 16 * ROWF * 4 + (ks + 1) * 32));
                #pragma unroll
                for (int fp = 0; fp < 4; ++fp)
                    ldsm4(bfr[nb][fp],
                          bbase + (uint32_t)(fp * 16 * ROWF * 4 + (ks + 1) * 32));
            } else if (it + 1 < TOT_IT) {
                // Stage boundary BEFORE the final MMA block: wait for the next
                // stage, barrier, prefetch its ks=0 fragments. ks=3 MMAs below
                // run from registers and cover this ldsm chain.
                if (it == TOT_IT - 2) { CP_WAIT0(); } else { CP_WAIT1(); }
                __syncthreads();
                #pragma unroll
                for (int fm = 0; fm < 4; ++fm)
                    ldsm4(afr[nb][fm], abase_n + (uint32_t)(fm * 16 * ROWF * 4));
                #pragma unroll
                for (int fp = 0; fp < 4; ++fp)
                    ldsm4(bfr[nb][fp], bbase_n + (uint32_t)(fp * 16 * ROWF * 4));
            }

            // Deferred cp.async burst: off the critical post-barrier path.
            if (ks == 1 && it + 2 < TOT_IT) issue(it + 2);

            // Prefetch epilogue elg block into L2 (one-off, non-critical slot).
            if (ks == 2 && it == 27) {
                const int q = lane & 3, grp = lane >> 2;
                const int col = nt * BN + warp_n * 64 + q * 2;
                #pragma unroll
                for (int fm = 0; fm < 4; ++fm) {
                    const size_t rowA = row0 + warp_m * 64 + fm * 16 + grp;
                    prefetch_l2(elg + rowA * (size_t)DDIM + col);
                    prefetch_l2(elg + (rowA + 8) * (size_t)DDIM + col);
                }
            }

            #pragma unroll
            for (int fm = 0; fm < 4; ++fm)
                #pragma unroll
                for (int fn = 0; fn < 8; ++fn)
                    mma_tf32(acc[fm][fn], afr[cb][fm],
                             bfr[cb][fn >> 1][(fn & 1) * 2 + 0],
                             bfr[cb][fn >> 1][(fn & 1) * 2 + 1]);
        }
        cur = nxt;
    }

    // Epilogue: fold acc into per-row partials against elg, reduce, atomicAdd.
    float part[8];
    #pragma unroll
    for (int i = 0; i < 8; ++i) part[i] = 0.0f;
    {
        const int q = lane & 3, grp = lane >> 2;
        #pragma unroll
        for (int fm = 0; fm < 4; ++fm) {
            const size_t rowA = row0 + warp_m * 64 + fm * 16 + grp;
            #pragma unroll
            for (int fn = 0; fn < 8; ++fn) {
                const int col = nt * BN + warp_n * 64 + fn * 8 + q * 2;
                const float2 e0 = *reinterpret_cast<const float2*>(
                    elg + rowA * (size_t)DDIM + col);
                const float2 e1 = *reinterpret_cast<const float2*>(
                    elg + (rowA + 8) * (size_t)DDIM + col);
                part[fm * 2 + 0] = fmaf(acc[fm][fn][0], e0.x,
                                   fmaf(acc[fm][fn][1], e0.y, part[fm * 2 + 0]));
                part[fm * 2 + 1] = fmaf(acc[fm][fn][2], e1.x,
                                   fmaf(acc[fm][fn][3], e1.y, part[fm * 2 + 1]));
            }
        }
    }

    __syncthreads();
    #pragma unroll
    for (int i = 0; i < 8; ++i) {
        part[i] += __shfl_xor_sync(0xFFFFFFFFu, part[i], 1);
        part[i] += __shfl_xor_sync(0xFFFFFFFFu, part[i], 2);
    }
    float* red = smem;                // [2][128]
    if ((lane & 3) == 0) {
        const int grp = lane >> 2;
        #pragma unroll
        for (int fm = 0; fm < 4; ++fm) {
            red[warp_n * 128 + warp_m * 64 + fm * 16 + grp]     = part[fm * 2 + 0];
            red[warp_n * 128 + warp_m * 64 + fm * 16 + grp + 8] = part[fm * 2 + 1];
        }
    }
    __syncthreads();
    atomicAdd(&out[row0 + tid], red[tid] + red[128 + tid]);
}

// ------------------------------- launch ------------------------------------

extern "C" void kernel_launch(void* const* d_in, const int* in_sizes, int n_in,
                              void* d_out, int out_size) {
    (void)in_sizes; (void)n_in; (void)out_size;
    const float* elg = (const float*)d_in[0];
    const float* eth = (const float*)d_in[1];
    const float* Wm  = (const float*)d_in[2];
    float* out = (float*)d_out;

    float* W_t = nullptr;
    cudaGetSymbolAddress((void**)&W_t, g_W_t);

    prep_kernel<<<148, 256>>>(Wm, W_t, out);

    cudaFuncSetAttribute(bilinear_tf32_kernel,
                         cudaFuncAttributeMaxDynamicSharedMemorySize, SMEM_B);
    dim3 grid(DDIM / BN, NROWS / BM);   // x = n-tile (fastest), y = row block
    bilinear_tf32_kernel<<<grid, 128, SMEM_B>>>(elg, eth, W_t, out);
}

// round 16
// speedup vs baseline: 2.8932x; 1.5699x over previous
#include <cuda_runtime.h>
#include <cuda_fp16.h>
#include <cstdint>

// ---------------------------------------------------------------------------
// out[n] = elg[n] @ W @ eth[n],  N=32768, D=1024, fp32.
// R14: fp16 MMA path. fp16 has the same 10-bit mantissa as tf32 but
// m16n8k16 does 2x the MACs per instruction -> tensor floor halves.
// eth and W are RN-converted to fp16 by a prepass; accumulation is fp32;
// elg epilogue stays fp32. Structure = R13: grid (8,256) nt-fastest,
// 128x128 tile (BK=64 now), 4 fat warps 64x64, 3-stage cp.async,
// 4-slot k-slice register double buffering, barrier rotated into ks=3,
// cp.async burst deferred to ks=1, fused elg epilogue + atomicAdd.
// ---------------------------------------------------------------------------

static constexpr int NROWS = 32768;
static constexpr int DDIM  = 1024;
static constexpr int BM = 128, BN = 128, BK = 64;
static constexpr int KITERS  = DDIM / BK;            // 16
static constexpr int TOT_IT  = KITERS;               // one n-tile per CTA

static constexpr int ROWH     = 72;                  // fp16 per padded row (144 B)
static constexpr int ROWB     = ROWH * 2;            // 144 bytes
static constexpr int A_TILE_B = BM * ROWB;           // 18432
static constexpr int B_TILE_B = BN * ROWB;           // 18432
static constexpr int STAGE_B  = A_TILE_B + B_TILE_B; // 36864
static constexpr int NSTAGES  = 3;
static constexpr int SMEM_B   = NSTAGES * STAGE_B;   // 110592

__device__ __half g_eth_h[(size_t)NROWS * DDIM];     // 64 MB fp16 eth
__device__ __half g_W_h[(size_t)DDIM * DDIM];        // 2 MB fp16 W

__device__ __forceinline__ uint32_t smem_u32(const void* p) {
    uint32_t a;
    asm("{ .reg .u64 t; cvta.to.shared.u64 t, %1; cvt.u32.u64 %0, t; }" : "=r"(a) : "l"(p));
    return a;
}

__device__ __forceinline__ void cp16(uint32_t saddr, const void* g) {
    asm volatile("cp.async.cg.shared.global [%0], [%1], 16;\n" :: "r"(saddr), "l"(g));
}
#define CP_COMMIT() asm volatile("cp.async.commit_group;\n" ::: "memory")
#define CP_WAIT1()  asm volatile("cp.async.wait_group 1;\n" ::: "memory")
#define CP_WAIT0()  asm volatile("cp.async.wait_group 0;\n" ::: "memory")

__device__ __forceinline__ void ldsm4(uint32_t (&d)[4], uint32_t addr) {
    asm volatile("ldmatrix.sync.aligned.m8n8.x4.shared.b16 {%0,%1,%2,%3}, [%4];"
                 : "=r"(d[0]), "=r"(d[1]), "=r"(d[2]), "=r"(d[3]) : "r"(addr));
}

__device__ __forceinline__ void prefetch_l2(const void* p) {
    asm volatile("prefetch.global.L2 [%0];" :: "l"(p));
}

__device__ __forceinline__ void mma_f16(float (&c)[4], const uint32_t (&a)[4],
                                        uint32_t b0, uint32_t b1) {
    asm volatile(
        "mma.sync.aligned.m16n8k16.row.col.f32.f16.f16.f32 "
        "{%0,%1,%2,%3}, {%4,%5,%6,%7}, {%8,%9}, {%0,%1,%2,%3};"
        : "+f"(c[0]), "+f"(c[1]), "+f"(c[2]), "+f"(c[3])
        : "r"(a[0]), "r"(a[1]), "r"(a[2]), "r"(a[3]), "r"(b0), "r"(b1));
}

// ------------- prep: fp32->fp16 RN convert eth + W, zero out ---------------

static constexpr int ETH4 = (NROWS * DDIM) / 4;      // 8M float4
static constexpr int W4   = (DDIM * DDIM) / 4;
static constexpr int OUT4 = NROWS / 4;

__global__ void __launch_bounds__(256)
prep_kernel(const float* __restrict__ ethsrc, __half* __restrict__ ethdst,
            const float* __restrict__ Wsrc, __half* __restrict__ Wdst,
            float* __restrict__ outz)
{
    const int gid = blockIdx.x * blockDim.x + threadIdx.x;
    const int stride = gridDim.x * blockDim.x;
    union Pack { uint2 u; __half2 h[2]; };
    for (int i = gid; i < ETH4; i += stride) {
        float4 v = reinterpret_cast<const float4*>(ethsrc)[i];
        Pack p;
        p.h[0] = __floats2half2_rn(v.x, v.y);
        p.h[1] = __floats2half2_rn(v.z, v.w);
        reinterpret_cast<uint2*>(ethdst)[i] = p.u;
    }
    for (int i = gid; i < W4; i += stride) {
        float4 v = reinterpret_cast<const float4*>(Wsrc)[i];
        Pack p;
        p.h[0] = __floats2half2_rn(v.x, v.y);
        p.h[1] = __floats2half2_rn(v.z, v.w);
        reinterpret_cast<uint2*>(Wdst)[i] = p.u;
    }
    for (int i = gid; i < OUT4; i += stride)
        reinterpret_cast<float4*>(outz)[i] = make_float4(0.f, 0.f, 0.f, 0.f);
}

// ------------------------------- main kernel -------------------------------

__global__ void __launch_bounds__(128, 2)
bilinear_f16_kernel(const float* __restrict__ elg, const __half* __restrict__ ethh,
                    const __half* __restrict__ Wh, float* __restrict__ out)
{
    extern __shared__ __align__(16) float smem[];
    const uint32_t sbase = smem_u32(smem);

    const int tid    = threadIdx.x;
    const int lane   = tid & 31;
    const int wid    = tid >> 5;      // 0..3
    const int warp_m = wid >> 1;      // 0..1
    const int warp_n = wid & 1;       // 0..1
    const int nt     = blockIdx.x;    // 0..7 (fastest-varying)
    const size_t row0 = (size_t)blockIdx.y * BM;

    // ldmatrix lane mapping. A (16x16 frag, x4): tiles = (rows0-7,k0),(rows8-15,k0),
    // (rows0-7,k8),(rows8-15,k8). B (two n8 x k16 frags per x4): tiles =
    // (n0-7,k0),(n0-7,k8),(n8-15,k0),(n8-15,k8).
    const int t = lane >> 3, r = lane & 7;
    const uint32_t aoff = (uint32_t)(((t & 1) * 8 + r) * ROWB + ((t >> 1) * 8) * 2);
    const uint32_t boff = (uint32_t)(((t >> 1) * 8 + r) * ROWB + ((t & 1) * 8) * 2);
    const uint32_t a_warp = (uint32_t)(warp_m * 64 * ROWB);
    const uint32_t b_warp = (uint32_t)(warp_n * 64 * ROWB);

    float acc[4][8][4];
    #pragma unroll
    for (int i = 0; i < 4; ++i)
        #pragma unroll
        for (int j = 0; j < 8; ++j)
            #pragma unroll
            for (int k = 0; k < 4; ++k) acc[i][j][k] = 0.0f;

    auto issue = [&](int jt) {
        const int kc = jt, st = jt % NSTAGES;
        const uint32_t ab = sbase + st * STAGE_B;
        const uint32_t bb = ab + A_TILE_B;
        #pragma unroll
        for (int u = 0; u < 8; ++u) {               // A: 128 rows x 8 x (8 fp16)
            const int idx = tid + u * 128;          // 0..1023
            const int m = idx >> 3, c8 = idx & 7;
            cp16(ab + (uint32_t)(m * ROWB + c8 * 16),
                 ethh + (row0 + m) * (size_t)DDIM + kc * BK + c8 * 8);
        }
        #pragma unroll
        for (int u = 0; u < 8; ++u) {               // B: 128 rows x 8 x (8 fp16)
            const int idx = tid + u * 128;
            const int n = idx >> 3, c8 = idx & 7;
            cp16(bb + (uint32_t)(n * ROWB + c8 * 16),
                 Wh + (size_t)(nt * BN + n) * DDIM + kc * BK + c8 * 8);
        }
        CP_COMMIT();
    };

    issue(0);
    issue(1);

    // Prologue: stage 0 resident, load its ks=0 fragments into buffer 0.
    uint32_t afr[2][4][4];
    uint32_t bfr[2][4][4];

    CP_WAIT1();
    __syncthreads();
    {
        const uint32_t ab0 = sbase + a_warp + aoff;
        const uint32_t bb0 = sbase + A_TILE_B + b_warp + boff;
        #pragma unroll
        for (int fm = 0; fm < 4; ++fm)
            ldsm4(afr[0][fm], ab0 + (uint32_t)(fm * 16 * ROWB));
        #pragma unroll
        for (int fp = 0; fp < 4; ++fp)
            ldsm4(bfr[0][fp], bb0 + (uint32_t)(fp * 16 * ROWB));
    }

    int cur = 0;
    for (int it = 0; it < TOT_IT; ++it) {
        const uint32_t abase = sbase + cur * STAGE_B + a_warp + aoff;
        const uint32_t bbase = sbase + cur * STAGE_B + A_TILE_B + b_warp + boff;
        const int nxt = (cur + 1 == NSTAGES) ? 0 : cur + 1;
        const uint32_t abase_n = sbase + nxt * STAGE_B + a_warp + aoff;
        const uint32_t bbase_n = sbase + nxt * STAGE_B + A_TILE_B + b_warp + boff;

        #pragma unroll
        for (int ks = 0; ks < 4; ++ks) {            // 4 k16-slices per BK=64
            const int cb = ks & 1, nb = cb ^ 1;
            if (ks < 3) {
                // Fragments for k-slice ks+1 of this stage (16 fp16 = 32 B step).
                #pragma unroll
                for (int fm = 0; fm < 4; ++fm)
                    ldsm4(afr[nb][fm],
                          abase + (uint32_t)(fm * 16 * ROWB + (ks + 1) * 32));
                #pragma unroll
                for (int fp = 0; fp < 4; ++fp)
                    ldsm4(bfr[nb][fp],
                          bbase + (uint32_t)(fp * 16 * ROWB + (ks + 1) * 32));
            } else if (it + 1 < TOT_IT) {
                // Stage boundary BEFORE the final MMA block: wait, barrier,
                // prefetch the next stage's ks=0 fragments; ks=3 MMAs below
                // run from registers and cover this ldsm chain.
                if (it == TOT_IT - 2) { CP_WAIT0(); } else { CP_WAIT1(); }
                __syncthreads();
                #pragma unroll
                for (int fm = 0; fm < 4; ++fm)
                    ldsm4(afr[nb][fm], abase_n + (uint32_t)(fm * 16 * ROWB));
                #pragma unroll
                for (int fp = 0; fp < 4; ++fp)
                    ldsm4(bfr[nb][fp], bbase_n + (uint32_t)(fp * 16 * ROWB));
            }

            // Deferred cp.async burst: off the critical post-barrier path.
            if (ks == 1 && it + 2 < TOT_IT) issue(it + 2);

            // Prefetch epilogue elg block into L2 (one-off, non-critical slot).
            if (ks == 2 && it == TOT_IT - 3) {
                const int q = lane & 3, grp = lane >> 2;
                const int col = nt * BN + warp_n * 64 + q * 2;
                #pragma unroll
                for (int fm = 0; fm < 4; ++fm) {
                    const size_t rowA = row0 + warp_m * 64 + fm * 16 + grp;
                    prefetch_l2(elg + rowA * (size_t)DDIM + col);
                    prefetch_l2(elg + (rowA + 8) * (size_t)DDIM + col);
                }
            }

            #pragma unroll
            for (int fm = 0; fm < 4; ++fm)
                #pragma unroll
                for (int fn = 0; fn < 8; ++fn)
                    mma_f16(acc[fm][fn], afr[cb][fm],
                            bfr[cb][fn >> 1][(fn & 1) * 2 + 0],
                            bfr[cb][fn >> 1][(fn & 1) * 2 + 1]);
        }
        cur = nxt;
    }

    // Epilogue: fold acc into per-row partials against elg, reduce, atomicAdd.
    float part[8];
    #pragma unroll
    for (int i = 0; i < 8; ++i) part[i] = 0.0f;
    {
        const int q = lane & 3, grp = lane >> 2;
        #pragma unroll
        for (int fm = 0; fm < 4; ++fm) {
            const size_t rowA = row0 + warp_m * 64 + fm * 16 + grp;
            #pragma unroll
            for (int fn = 0; fn < 8; ++fn) {
                const int col = nt * BN + warp_n * 64 + fn * 8 + q * 2;
                const float2 e0 = *reinterpret_cast<const float2*>(
                    elg + rowA * (size_t)DDIM + col);
                const float2 e1 = *reinterpret_cast<const float2*>(
                    elg + (rowA + 8) * (size_t)DDIM + col);
                part[fm * 2 + 0] = fmaf(acc[fm][fn][0], e0.x,
                                   fmaf(acc[fm][fn][1], e0.y, part[fm * 2 + 0]));
                part[fm * 2 + 1] = fmaf(acc[fm][fn][2], e1.x,
                                   fmaf(acc[fm][fn][3], e1.y, part[fm * 2 + 1]));
            }
        }
    }

    __syncthreads();
    #pragma unroll
    for (int i = 0; i < 8; ++i) {
        part[i] += __shfl_xor_sync(0xFFFFFFFFu, part[i], 1);
        part[i] += __shfl_xor_sync(0xFFFFFFFFu, part[i], 2);
    }
    float* red = smem;                // [2][128]
    if ((lane & 3) == 0) {
        const int grp = lane >> 2;
        #pragma unroll
        for (int fm = 0; fm < 4; ++fm) {
            red[warp_n * 128 + warp_m * 64 + fm * 16 + grp]     = part[fm * 2 + 0];
            red[warp_n * 128 + warp_m * 64 + fm * 16 + grp + 8] = part[fm * 2 + 1];
        }
    }
    __syncthreads();
    atomicAdd(&out[row0 + tid], red[tid] + red[128 + tid]);
}

// ------------------------------- launch ------------------------------------

extern "C" void kernel_launch(void* const* d_in, const int* in_sizes, int n_in,
                              void* d_out, int out_size) {
    (void)in_sizes; (void)n_in; (void)out_size;
    const float* elg = (const float*)d_in[0];
    const float* eth = (const float*)d_in[1];
    const float* Wm  = (const float*)d_in[2];
    float* out = (float*)d_out;

    __half* eth_h = nullptr;
    __half* W_h   = nullptr;
    cudaGetSymbolAddress((void**)&eth_h, g_eth_h);
    cudaGetSymbolAddress((void**)&W_h,   g_W_h);

    prep_kernel<<<592, 256>>>(eth, eth_h, Wm, W_h, out);

    cudaFuncSetAttribute(bilinear_f16_kernel,
                         cudaFuncAttributeMaxDynamicSharedMemorySize, SMEM_B);
    dim3 grid(DDIM / BN, NROWS / BM);   // x = n-tile (fastest), y = row block
    bilinear_f16_kernel<<<grid, 128, SMEM_B>>>(elg, eth_h, W_h, out);
}

// round 17
// speedup vs baseline: 2.9737x; 1.0278x over previous
#include <cuda_runtime.h>
#include <cuda_fp16.h>
#include <cstdint>

// ---------------------------------------------------------------------------
// out[n] = elg[n] @ W @ eth[n],  N=32768, D=1024, fp32.
// R15: R14 (fp16 m16n8k16 path, grid (8,256) nt-fastest, 128x128 tile BK=64,
// 4 fat warps 64x64, 3-stage cp.async, rotated barrier, deferred cp.async)
// with micro-exposure fixes: full-span elg L2 prefetch (both 128B lines),
// load-batched epilogue (explicit MLP per fm), wider prepass grid.
// ---------------------------------------------------------------------------

static constexpr int NROWS = 32768;
static constexpr int DDIM  = 1024;
static constexpr int BM = 128, BN = 128, BK = 64;
static constexpr int KITERS  = DDIM / BK;            // 16
static constexpr int TOT_IT  = KITERS;               // one n-tile per CTA

static constexpr int ROWH     = 72;                  // fp16 per padded row (144 B)
static constexpr int ROWB     = ROWH * 2;            // 144 bytes
static constexpr int A_TILE_B = BM * ROWB;           // 18432
static constexpr int B_TILE_B = BN * ROWB;           // 18432
static constexpr int STAGE_B  = A_TILE_B + B_TILE_B; // 36864
static constexpr int NSTAGES  = 3;
static constexpr int SMEM_B   = NSTAGES * STAGE_B;   // 110592

__device__ __half g_eth_h[(size_t)NROWS * DDIM];     // 64 MB fp16 eth
__device__ __half g_W_h[(size_t)DDIM * DDIM];        // 2 MB fp16 W

__device__ __forceinline__ uint32_t smem_u32(const void* p) {
    uint32_t a;
    asm("{ .reg .u64 t; cvta.to.shared.u64 t, %1; cvt.u32.u64 %0, t; }" : "=r"(a) : "l"(p));
    return a;
}

__device__ __forceinline__ void cp16(uint32_t saddr, const void* g) {
    asm volatile("cp.async.cg.shared.global [%0], [%1], 16;\n" :: "r"(saddr), "l"(g));
}
#define CP_COMMIT() asm volatile("cp.async.commit_group;\n" ::: "memory")
#define CP_WAIT1()  asm volatile("cp.async.wait_group 1;\n" ::: "memory")
#define CP_WAIT0()  asm volatile("cp.async.wait_group 0;\n" ::: "memory")

__device__ __forceinline__ void ldsm4(uint32_t (&d)[4], uint32_t addr) {
    asm volatile("ldmatrix.sync.aligned.m8n8.x4.shared.b16 {%0,%1,%2,%3}, [%4];"
                 : "=r"(d[0]), "=r"(d[1]), "=r"(d[2]), "=r"(d[3]) : "r"(addr));
}

__device__ __forceinline__ void prefetch_l2(const void* p) {
    asm volatile("prefetch.global.L2 [%0];" :: "l"(p));
}

__device__ __forceinline__ void mma_f16(float (&c)[4], const uint32_t (&a)[4],
                                        uint32_t b0, uint32_t b1) {
    asm volatile(
        "mma.sync.aligned.m16n8k16.row.col.f32.f16.f16.f32 "
        "{%0,%1,%2,%3}, {%4,%5,%6,%7}, {%8,%9}, {%0,%1,%2,%3};"
        : "+f"(c[0]), "+f"(c[1]), "+f"(c[2]), "+f"(c[3])
        : "r"(a[0]), "r"(a[1]), "r"(a[2]), "r"(a[3]), "r"(b0), "r"(b1));
}

// ------------- prep: fp32->fp16 RN convert eth + W, zero out ---------------

static constexpr int ETH4 = (NROWS * DDIM) / 4;      // 8M float4
static constexpr int W4   = (DDIM * DDIM) / 4;
static constexpr int OUT4 = NROWS / 4;

__global__ void __launch_bounds__(256)
prep_kernel(const float* __restrict__ ethsrc, __half* __restrict__ ethdst,
            const float* __restrict__ Wsrc, __half* __restrict__ Wdst,
            float* __restrict__ outz)
{
    const int gid = blockIdx.x * blockDim.x + threadIdx.x;
    const int stride = gridDim.x * blockDim.x;
    union Pack { uint2 u; __half2 h[2]; };
    for (int i = gid; i < ETH4; i += stride) {
        float4 v = reinterpret_cast<const float4*>(ethsrc)[i];
        Pack p;
        p.h[0] = __floats2half2_rn(v.x, v.y);
        p.h[1] = __floats2half2_rn(v.z, v.w);
        reinterpret_cast<uint2*>(ethdst)[i] = p.u;
    }
    for (int i = gid; i < W4; i += stride) {
        float4 v = reinterpret_cast<const float4*>(Wsrc)[i];
        Pack p;
        p.h[0] = __floats2half2_rn(v.x, v.y);
        p.h[1] = __floats2half2_rn(v.z, v.w);
        reinterpret_cast<uint2*>(Wdst)[i] = p.u;
    }
    for (int i = gid; i < OUT4; i += stride)
        reinterpret_cast<float4*>(outz)[i] = make_float4(0.f, 0.f, 0.f, 0.f);
}

// ------------------------------- main kernel -------------------------------

__global__ void __launch_bounds__(128, 2)
bilinear_f16_kernel(const float* __restrict__ elg, const __half* __restrict__ ethh,
                    const __half* __restrict__ Wh, float* __restrict__ out)
{
    extern __shared__ __align__(16) float smem[];
    const uint32_t sbase = smem_u32(smem);

    const int tid    = threadIdx.x;
    const int lane   = tid & 31;
    const int wid    = tid >> 5;      // 0..3
    const int warp_m = wid >> 1;      // 0..1
    const int warp_n = wid & 1;       // 0..1
    const int nt     = blockIdx.x;    // 0..7 (fastest-varying)
    const size_t row0 = (size_t)blockIdx.y * BM;

    // ldmatrix lane mapping (see R14).
    const int t = lane >> 3, r = lane & 7;
    const uint32_t aoff = (uint32_t)(((t & 1) * 8 + r) * ROWB + ((t >> 1) * 8) * 2);
    const uint32_t boff = (uint32_t)(((t >> 1) * 8 + r) * ROWB + ((t & 1) * 8) * 2);
    const uint32_t a_warp = (uint32_t)(warp_m * 64 * ROWB);
    const uint32_t b_warp = (uint32_t)(warp_n * 64 * ROWB);

    float acc[4][8][4];
    #pragma unroll
    for (int i = 0; i < 4; ++i)
        #pragma unroll
        for (int j = 0; j < 8; ++j)
            #pragma unroll
            for (int k = 0; k < 4; ++k) acc[i][j][k] = 0.0f;

    auto issue = [&](int jt) {
        const int kc = jt, st = jt % NSTAGES;
        const uint32_t ab = sbase + st * STAGE_B;
        const uint32_t bb = ab + A_TILE_B;
        #pragma unroll
        for (int u = 0; u < 8; ++u) {               // A: 128 rows x 8 x (8 fp16)
            const int idx = tid + u * 128;          // 0..1023
            const int m = idx >> 3, c8 = idx & 7;
            cp16(ab + (uint32_t)(m * ROWB + c8 * 16),
                 ethh + (row0 + m) * (size_t)DDIM + kc * BK + c8 * 8);
        }
        #pragma unroll
        for (int u = 0; u < 8; ++u) {               // B: 128 rows x 8 x (8 fp16)
            const int idx = tid + u * 128;
            const int n = idx >> 3, c8 = idx & 7;
            cp16(bb + (uint32_t)(n * ROWB + c8 * 16),
                 Wh + (size_t)(nt * BN + n) * DDIM + kc * BK + c8 * 8);
        }
        CP_COMMIT();
    };

    issue(0);
    issue(1);

    // Prologue: stage 0 resident, load its ks=0 fragments into buffer 0.
    uint32_t afr[2][4][4];
    uint32_t bfr[2][4][4];

    CP_WAIT1();
    __syncthreads();
    {
        const uint32_t ab0 = sbase + a_warp + aoff;
        const uint32_t bb0 = sbase + A_TILE_B + b_warp + boff;
        #pragma unroll
        for (int fm = 0; fm < 4; ++fm)
            ldsm4(afr[0][fm], ab0 + (uint32_t)(fm * 16 * ROWB));
        #pragma unroll
        for (int fp = 0; fp < 4; ++fp)
            ldsm4(bfr[0][fp], bb0 + (uint32_t)(fp * 16 * ROWB));
    }

    int cur = 0;
    for (int it = 0; it < TOT_IT; ++it) {
        const uint32_t abase = sbase + cur * STAGE_B + a_warp + aoff;
        const uint32_t bbase = sbase + cur * STAGE_B + A_TILE_B + b_warp + boff;
        const int nxt = (cur + 1 == NSTAGES) ? 0 : cur + 1;
        const uint32_t abase_n = sbase + nxt * STAGE_B + a_warp + aoff;
        const uint32_t bbase_n = sbase + nxt * STAGE_B + A_TILE_B + b_warp + boff;

        #pragma unroll
        for (int ks = 0; ks < 4; ++ks) {            // 4 k16-slices per BK=64
            const int cb = ks & 1, nb = cb ^ 1;
            if (ks < 3) {
                #pragma unroll
                for (int fm = 0; fm < 4; ++fm)
                    ldsm4(afr[nb][fm],
                          abase + (uint32_t)(fm * 16 * ROWB + (ks + 1) * 32));
                #pragma unroll
                for (int fp = 0; fp < 4; ++fp)
                    ldsm4(bfr[nb][fp],
                          bbase + (uint32_t)(fp * 16 * ROWB + (ks + 1) * 32));
            } else if (it + 1 < TOT_IT) {
                if (it == TOT_IT - 2) { CP_WAIT0(); } else { CP_WAIT1(); }
                __syncthreads();
                #pragma unroll
                for (int fm = 0; fm < 4; ++fm)
                    ldsm4(afr[nb][fm], abase_n + (uint32_t)(fm * 16 * ROWB));
                #pragma unroll
                for (int fp = 0; fp < 4; ++fp)
                    ldsm4(bfr[nb][fp], bbase_n + (uint32_t)(fp * 16 * ROWB));
            }

            // Deferred cp.async burst: off the critical post-barrier path.
            if (ks == 1 && it + 2 < TOT_IT) issue(it + 2);

            // Epilogue elg L2 prefetch: full 64-float span = two 128B lines
            // per row, split across two non-critical slots.
            if (it == TOT_IT - 4 && (ks == 1 || ks == 2)) {
                const int grp = lane >> 2;
                const int colb = nt * BN + warp_n * 64 + (ks == 2 ? 32 : 0);
                #pragma unroll
                for (int fm = 0; fm < 4; ++fm) {
                    const size_t rowA = row0 + warp_m * 64 + fm * 16 + grp;
                    prefetch_l2(elg + rowA * (size_t)DDIM + colb);
                    prefetch_l2(elg + (rowA + 8) * (size_t)DDIM + colb);
                }
            }

            #pragma unroll
            for (int fm = 0; fm < 4; ++fm)
                #pragma unroll
                for (int fn = 0; fn < 8; ++fn)
                    mma_f16(acc[fm][fn], afr[cb][fm],
                            bfr[cb][fn >> 1][(fn & 1) * 2 + 0],
                            bfr[cb][fn >> 1][(fn & 1) * 2 + 1]);
        }
        cur = nxt;
    }

    // Epilogue: per fm, batch all 16 independent elg loads (explicit MLP),
    // then run the FMA chain. Fold into per-row partials, reduce, atomicAdd.
    float part[8];
    #pragma unroll
    for (int i = 0; i < 8; ++i) part[i] = 0.0f;
    {
        const int q = lane & 3, grp = lane >> 2;
        #pragma unroll
        for (int fm = 0; fm < 4; ++fm) {
            const size_t rowA = row0 + warp_m * 64 + fm * 16 + grp;
            const float* p0 = elg + rowA * (size_t)DDIM;
            const float* p1 = elg + (rowA + 8) * (size_t)DDIM;
            float2 e0[8], e1[8];
            #pragma unroll
            for (int fn = 0; fn < 8; ++fn) {
                const int col = nt * BN + warp_n * 64 + fn * 8 + q * 2;
                e0[fn] = *reinterpret_cast<const float2*>(p0 + col);
                e1[fn] = *reinterpret_cast<const float2*>(p1 + col);
            }
            #pragma unroll
            for (int fn = 0; fn < 8; ++fn) {
                part[fm * 2 + 0] = fmaf(acc[fm][fn][0], e0[fn].x,
                                   fmaf(acc[fm][fn][1], e0[fn].y, part[fm * 2 + 0]));
                part[fm * 2 + 1] = fmaf(acc[fm][fn][2], e1[fn].x,
                                   fmaf(acc[fm][fn][3], e1[fn].y, part[fm * 2 + 1]));
            }
        }
    }

    __syncthreads();
    #pragma unroll
    for (int i = 0; i < 8; ++i) {
        part[i] += __shfl_xor_sync(0xFFFFFFFFu, part[i], 1);
        part[i] += __shfl_xor_sync(0xFFFFFFFFu, part[i], 2);
    }
    float* red = smem;                // [2][128]
    if ((lane & 3) == 0) {
        const int grp = lane >> 2;
        #pragma unroll
        for (int fm = 0; fm < 4; ++fm) {
            red[warp_n * 128 + warp_m * 64 + fm * 16 + grp]     = part[fm * 2 + 0];
            red[warp_n * 128 + warp_m * 64 + fm * 16 + grp + 8] = part[fm * 2 + 1];
        }
    }
    __syncthreads();
    atomicAdd(&out[row0 + tid], red[tid] + red[128 + tid]);
}

// ------------------------------- launch ------------------------------------

extern "C" void kernel_launch(void* const* d_in, const int* in_sizes, int n_in,
                              void* d_out, int out_size) {
    (void)in_sizes; (void)n_in; (void)out_size;
    const float* elg = (const float*)d_in[0];
    const float* eth = (const float*)d_in[1];
    const float* Wm  = (const float*)d_in[2];
    float* out = (float*)d_out;

    __half* eth_h = nullptr;
    __half* W_h   = nullptr;
    cudaGetSymbolAddress((void**)&eth_h, g_eth_h);
    cudaGetSymbolAddress((void**)&W_h,   g_W_h);

    prep_kernel<<<1184, 256>>>(eth, eth_h, Wm, W_h, out);

    cudaFuncSetAttribute(bilinear_f16_kernel,
                         cudaFuncAttributeMaxDynamicSharedMemorySize, SMEM_B);
    dim3 grid(DDIM / BN, NROWS / BM);   // x = n-tile (fastest), y = row block
    bilinear_f16_kernel<<<grid, 128, SMEM_B>>>(elg, eth_h, W_h, out);
}